// round 15
// baseline (speedup 1.0000x reference)
#include <cuda_runtime.h>
#include <cstdint>

#define NB 32
#define NIMG 640
#define CH 50176
#define IMG_SZ 150528

__device__ float g_backbone[2 * NIMG * 6];

// backbone dynamic smem layout (floats)
#define O_BUF    0
#define O_CONV   9408
#define O_POOL1  11424
#define O_W2     15532
#define O_B1     15560
#define O_B2     15563
#define O_LW     15564
#define O_LB     15780
#define O_MBAR   15786
#define SMEM_FLOATS 15790
#define SMEM_BYTES  (SMEM_FLOATS * 4)

#define STRIP_BYTES 18816

// head dynamic smem layout (floats)
#define HF_WBUF  0        // 2 x 10800 weight chunk buffers (43200 B each)
#define HF_FEAT  21600    // 360
#define HF_H1P   21960    // 4 x 180
#define HF_H1    22680    // 180
#define HF_H2P   22860    // 12 x 60
#define HF_H2    23580    // 60
#define HF_H3P   23640    // 36
#define HF_MBAR  23676    // 2 x u64 (8B aligned)
#define HEAD_SMEM_FLOATS 23680
#define HEAD_SMEM_BYTES  (HEAD_SMEM_FLOATS * 4)   // 94720

#define CHUNK_BYTES 43200   // 60 rows x 180 cols x 4B

__device__ __forceinline__ uint32_t s2u(const void* p) {
    uint32_t a;
    asm("{ .reg .u64 t; cvta.to.shared.u64 t, %1; cvt.u32.u64 %0, t; }" : "=r"(a) : "l"(p));
    return a;
}
__device__ __forceinline__ void mbar_init(uint32_t a, uint32_t cnt) {
    asm volatile("mbarrier.init.shared.b64 [%0], %1;" :: "r"(a), "r"(cnt) : "memory");
}
__device__ __forceinline__ void mbar_expect(uint32_t a, uint32_t tx) {
    asm volatile("mbarrier.arrive.expect_tx.shared.b64 _, [%0], %1;" :: "r"(a), "r"(tx) : "memory");
}
__device__ __forceinline__ void mbar_wait(uint32_t a, uint32_t par) {
    asm volatile(
        "{\n\t.reg .pred P;\n"
        "WL%=:\n\t"
        "mbarrier.try_wait.parity.acquire.cta.shared::cta.b64 P, [%0], %1, 0x989680;\n\t"
        "@!P bra WL%=;\n\t}"
        :: "r"(a), "r"(par) : "memory");
}
__device__ __forceinline__ void bulk_g2s(uint32_t dst, const float* src,
                                         uint32_t bytes, uint32_t mbar) {
    asm volatile(
        "cp.async.bulk.shared::cluster.global.mbarrier::complete_tx::bytes "
        "[%0], [%1], %2, [%3];"
        :: "r"(dst), "l"(src), "r"(bytes), "r"(mbar) : "memory");
}

__device__ __forceinline__ void issue_strip(uint32_t bufb, int buf, const float* src,
                                            uint32_t mbar) {
    mbar_expect(mbar, STRIP_BYTES);
    uint32_t dst = bufb + (uint32_t)buf * STRIP_BYTES;
    #pragma unroll
    for (int ic = 0; ic < 3; ic++)
        bulk_g2s(dst + ic * 6272, src + ic * CH, 6272, mbar);
}

__global__ __launch_bounds__(128)
void backbone_kernel(const float* __restrict__ nodes,
                     const float* __restrict__ depths,
                     const float* __restrict__ c1w,  const float* __restrict__ c1b,
                     const float* __restrict__ c2w,  const float* __restrict__ c2b,
                     const float* __restrict__ lw,   const float* __restrict__ lb,
                     const float* __restrict__ dc1w, const float* __restrict__ dc1b,
                     const float* __restrict__ dc2w, const float* __restrict__ dc2b,
                     const float* __restrict__ dlw,  const float* __restrict__ dlb)
{
    extern __shared__ float sm[];
    const int img = blockIdx.x;
    const int bb  = blockIdx.y;
    const int tid = threadIdx.x;

    const float* in  = (bb == 0 ? nodes : depths) + (size_t)img * IMG_SZ;
    const float* w1  = bb == 0 ? c1w : dc1w;
    const float* b1  = bb == 0 ? c1b : dc1b;
    const float* w2  = bb == 0 ? c2w : dc2w;
    const float* b2  = bb == 0 ? c2b : dc2b;
    const float* lwp = bb == 0 ? lw  : dlw;
    const float* lbp = bb == 0 ? lb  : dlb;

    const uint32_t bufb = s2u(sm + O_BUF);
    const uint32_t mb0  = s2u(sm + O_MBAR);
    const uint32_t mb1  = mb0 + 8;

    float W[81];
    #pragma unroll
    for (int i = 0; i < 81; i++) W[i] = __ldg(w1 + i);

    if (tid < 27) sm[O_W2 + tid] = w2[tid];
    if (tid < 3)  sm[O_B1 + tid] = b1[tid];
    if (tid == 0) sm[O_B2] = b2[0];
    for (int t = tid; t < 216; t += 128) sm[O_LW + t] = lwp[t];
    if (tid < 6)  sm[O_LB + tid] = lbp[tid];

    if (tid == 0) {
        mbar_init(mb0, 1);
        mbar_init(mb1, 1);
        asm volatile("fence.proxy.async.shared::cta;" ::: "memory");
    }
    __syncthreads();

    if (tid == 0) {
        issue_strip(bufb, 0, in, mb0);
        issue_strip(bufb, 1, in + 6 * 224, mb1);
    }

    for (int pr = 0; pr < 37; pr++) {
        const int b = pr & 1;
        mbar_wait(b ? mb1 : mb0, (pr >> 1) & 1);

        if (tid < 111) {
            const int x = tid;
            float a[3][3] = {{0.f,0.f,0.f},{0.f,0.f,0.f},{0.f,0.f,0.f}};
            #pragma unroll
            for (int ic = 0; ic < 3; ic++) {
                const float* rp = sm + O_BUF + b * 4704 + ic * 1568 + 2 * x;
                #pragma unroll
                for (int r = 0; r < 7; r++) {
                    float2 p = *reinterpret_cast<const float2*>(rp + r * 224);
                    float  q = rp[r * 224 + 2];
                    #pragma unroll
                    for (int j = 0; j < 3; j++) {
                        const int ky = r - 2 * j;
                        if (ky >= 0 && ky < 3) {
                            #pragma unroll
                            for (int oc = 0; oc < 3; oc++) {
                                const int wb = (oc * 3 + ic) * 9 + ky * 3;
                                a[j][oc] = fmaf(p.x, W[wb],
                                           fmaf(p.y, W[wb + 1],
                                           fmaf(q,   W[wb + 2], a[j][oc])));
                            }
                        }
                    }
                }
            }
            #pragma unroll
            for (int j = 0; j < 3; j++)
                #pragma unroll
                for (int oc = 0; oc < 3; oc++)
                    sm[O_CONV + b * 1008 + (oc * 3 + j) * 112 + x] = a[j][oc];
        }
        __syncthreads();

        if (tid == 0 && pr + 2 < 37)
            issue_strip(bufb, b, in + 6 * (pr + 2) * 224, b ? mb1 : mb0);

        if (tid < 111) {
            const int oc = tid / 37, px = tid % 37;
            float m = -1e30f;
            #pragma unroll
            for (int j = 0; j < 3; j++)
                #pragma unroll
                for (int i = 0; i < 3; i++)
                    m = fmaxf(m, sm[O_CONV + b * 1008 + (oc * 3 + j) * 112 + 3 * px + i]);
            sm[O_POOL1 + (oc * 37 + pr) * 37 + px] = fmaxf(m + sm[O_B1 + oc], 0.f);
        }
    }
    __syncthreads();

    for (int t2 = tid; t2 < 324; t2 += 128) {
        int cy = t2 / 18, cx = t2 % 18;
        float acc = 0.f;
        #pragma unroll
        for (int ic = 0; ic < 3; ic++)
            #pragma unroll
            for (int ky = 0; ky < 3; ky++)
                #pragma unroll
                for (int kx = 0; kx < 3; kx++)
                    acc = fmaf(sm[O_W2 + (ic * 3 + ky) * 3 + kx],
                               sm[O_POOL1 + (ic * 37 + 2 * cy + ky) * 37 + 2 * cx + kx],
                               acc);
        sm[O_CONV + t2] = acc;
    }
    __syncthreads();

    if (tid < 36) {
        int py = tid / 6, px = tid % 6;
        float m = -1e30f;
        #pragma unroll
        for (int i = 0; i < 3; i++)
            #pragma unroll
            for (int j = 0; j < 3; j++)
                m = fmaxf(m, sm[O_CONV + (3 * py + i) * 18 + 3 * px + j]);
        sm[O_CONV + 400 + tid] = fmaxf(m + sm[O_B2], 0.f);
    }
    __syncthreads();

    if (tid < 6) {
        float acc = sm[O_LB + tid];
        #pragma unroll
        for (int i = 0; i < 36; i++)
            acc = fmaf(sm[O_CONV + 400 + i], sm[O_LW + i * 6 + tid], acc);
        g_backbone[bb * (NIMG * 6) + img * 6 + tid] = acc;
    }
}

// ---------------------------------------------------------------------------
// Head: weights streamed through smem via bulk-TMA (6x 60-row chunks of o1w,
// double-buffered; o2w as a 7th chunk). FMA reads smem only.
// ---------------------------------------------------------------------------
__global__ __launch_bounds__(768)
void head_kernel(const float* __restrict__ pos,  const float* __restrict__ attmap,
                 const float* __restrict__ fmw,  const float* __restrict__ fmb,
                 const float* __restrict__ lmw,  const float* __restrict__ lmb,
                 const float* __restrict__ o1w,  const float* __restrict__ o1b,
                 const float* __restrict__ o2w,  const float* __restrict__ o2b,
                 const float* __restrict__ o3w,  const float* __restrict__ o3b,
                 float* __restrict__ out)
{
    extern __shared__ float hs[];
    const int bx = blockIdx.x;
    const int t  = threadIdx.x;

    const uint32_t wb  = s2u(hs + HF_WBUF);
    const uint32_t mb0 = s2u(hs + HF_MBAR);
    const uint32_t mb1 = mb0 + 8;

    // kick off the weight pipeline immediately (backbone-independent)
    if (t == 0) {
        mbar_init(mb0, 1);
        mbar_init(mb1, 1);
        asm volatile("fence.proxy.async.shared::cta;" ::: "memory");
        mbar_expect(mb0, CHUNK_BYTES);
        bulk_g2s(wb, o1w, CHUNK_BYTES, mb0);
        mbar_expect(mb1, CHUNK_BYTES);
        bulk_g2s(wb + CHUNK_BYTES, o1w + 10800, CHUNK_BYTES, mb1);
    }

    // backbone-independent message passing (warps 12-15)
    if (t >= 384 && t < 504) {
        int tt = t - 384;
        int f = tt / 24, n = (tt % 24) / 6, d = tt % 6;
        const float* pb = pos    + bx * 120;
        const float* ab = attmap + bx * 80;
        float acc = 0.f;
        #pragma unroll
        for (int m = 0; m < 4; m++) {
            float pm = __ldg(fmb + d);
            #pragma unroll
            for (int e = 0; e < 6; e++)
                pm = fmaf(__ldg(pb + f * 24 + m * 6 + e), __ldg(fmw + e * 6 + d), pm);
            acc = fmaf(__ldg(ab + f * 16 + m * 4 + n), pm, acc);
        }
        if (f >= 1) {
            float pv = __ldg(lmb + d);
            #pragma unroll
            for (int e = 0; e < 6; e++)
                pv = fmaf(__ldg(pb + (f - 1) * 24 + n * 6 + e), __ldg(lmw + e * 6 + d), pv);
            acc += pv;
        }
        hs[HF_FEAT + (f * 4 + n) * 18 + 12 + d] = acc;
    }

    asm volatile("griddepcontrol.wait;" ::: "memory");

    if (t < 120) {
        int f = t / 24, m = (t % 24) / 6, d = t % 6;
        int fm = f * 4 + m;
        int gi = ((bx * 5 + f) * 4 + m) * 6 + d;
        hs[HF_FEAT + fm * 18 + d]     = g_backbone[gi];
        hs[HF_FEAT + fm * 18 + 6 + d] = g_backbone[NIMG * 6 + gi];
    }
    __syncthreads();   // feat ready; mbar init visible to all

    // layer 1: 360 -> 180 over 6 chunks of 60 input rows.
    const int o1 = t % 180;
    const int s1 = t / 180;
    float acc1 = 0.f;
    for (int c = 0; c < 6; c++) {
        const int b = c & 1;
        mbar_wait(b ? mb1 : mb0, (c >> 1) & 1);
        if (t < 720) {
            const float* wrow = hs + HF_WBUF + b * 10800 + (15 * s1) * 180 + o1;
            const float* vp   = hs + HF_FEAT + 60 * c + 15 * s1;
            #pragma unroll
            for (int i = 0; i < 15; i++)
                acc1 = fmaf(vp[i], wrow[i * 180], acc1);
        }
        __syncthreads();   // all reads of buf b retired
        if (t == 0) {
            if (c + 2 < 6) {
                const uint32_t mb = b ? mb1 : mb0;
                mbar_expect(mb, CHUNK_BYTES);
                bulk_g2s(wb + b * CHUNK_BYTES, o1w + (c + 2) * 10800, CHUNK_BYTES, mb);
            } else if (c + 2 == 6) {   // c == 4: stage o2w into buf0
                mbar_expect(mb0, CHUNK_BYTES);
                bulk_g2s(wb, o2w, CHUNK_BYTES, mb0);
            }
        }
    }
    if (t < 720) hs[HF_H1P + s1 * 180 + o1] = acc1;
    __syncthreads();

    if (t < 180) {
        float a = o1b[t];
        #pragma unroll
        for (int s = 0; s < 4; s++) a += hs[HF_H1P + s * 180 + t];
        hs[HF_H1 + t] = fmaxf(a, 0.f);
    }
    __syncthreads();

    // layer 2: 180 -> 60 from staged o2w (buf0, mb0 parity 1)
    mbar_wait(mb0, 1);
    if (t < 720) {
        const int o2 = t % 60, s2 = t / 60;   // s2 in 0..11, 15 rows each
        float a2 = 0.f;
        const float* wrow = hs + HF_WBUF + (15 * s2) * 60 + o2;
        const float* vp   = hs + HF_H1 + 15 * s2;
        #pragma unroll
        for (int i = 0; i < 15; i++)
            a2 = fmaf(vp[i], wrow[i * 60], a2);
        hs[HF_H2P + s2 * 60 + o2] = a2;
    }
    __syncthreads();

    if (t < 60) {
        float a = o2b[t];
        #pragma unroll
        for (int s = 0; s < 12; s++) a += hs[HF_H2P + s * 60 + t];
        hs[HF_H2 + t] = fmaxf(a, 0.f);
    }
    __syncthreads();

    // layer 3: 60 -> 6, 6-way input split (weights tiny, direct LDG)
    if (t < 36) {
        int q = t / 6, o = t - q * 6;
        int base = q * 10;
        float a = 0.f;
        #pragma unroll
        for (int i = 0; i < 10; i++)
            a = fmaf(hs[HF_H2 + base + i], __ldg(o3w + (base + i) * 6 + o), a);
        hs[HF_H3P + q * 6 + o] = a;
    }
    __syncthreads();
    if (t < 6) {
        float a = o3b[t];
        #pragma unroll
        for (int q = 0; q < 6; q++) a += hs[HF_H3P + q * 6 + t];
        out[bx * 6 + t] = a;
    }
}

extern "C" void kernel_launch(void* const* d_in, const int* in_sizes, int n_in,
                              void* d_out, int out_size)
{
    const float* nodes  = (const float*)d_in[0];
    const float* pos    = (const float*)d_in[1];
    const float* attmap = (const float*)d_in[2];
    const float* depths = (const float*)d_in[3];
    const float* c1w  = (const float*)d_in[4];
    const float* c1b  = (const float*)d_in[5];
    const float* c2w  = (const float*)d_in[6];
    const float* c2b  = (const float*)d_in[7];
    const float* lw   = (const float*)d_in[8];
    const float* lb   = (const float*)d_in[9];
    const float* dc1w = (const float*)d_in[10];
    const float* dc1b = (const float*)d_in[11];
    const float* dc2w = (const float*)d_in[12];
    const float* dc2b = (const float*)d_in[13];
    const float* dlw  = (const float*)d_in[14];
    const float* dlb  = (const float*)d_in[15];
    const float* fmw  = (const float*)d_in[16];
    const float* fmb  = (const float*)d_in[17];
    const float* lmw  = (const float*)d_in[18];
    const float* lmb  = (const float*)d_in[19];
    const float* o1w  = (const float*)d_in[20];
    const float* o1b  = (const float*)d_in[21];
    const float* o2w  = (const float*)d_in[22];
    const float* o2b  = (const float*)d_in[23];
    const float* o3w  = (const float*)d_in[24];
    const float* o3b  = (const float*)d_in[25];

    cudaFuncSetAttribute(backbone_kernel,
                         cudaFuncAttributeMaxDynamicSharedMemorySize, SMEM_BYTES);
    cudaFuncSetAttribute(head_kernel,
                         cudaFuncAttributeMaxDynamicSharedMemorySize, HEAD_SMEM_BYTES);

    backbone_kernel<<<dim3(NIMG, 2), 128, SMEM_BYTES>>>(
        nodes, depths, c1w, c1b, c2w, c2b, lw, lb,
        dc1w, dc1b, dc2w, dc2b, dlw, dlb);

    cudaLaunchAttribute attrs[1];
    attrs[0].id = cudaLaunchAttributeProgrammaticStreamSerialization;
    attrs[0].val.programmaticStreamSerializationAllowed = 1;
    cudaLaunchConfig_t cfg = {};
    cfg.gridDim = dim3(NB);
    cfg.blockDim = dim3(768);
    cfg.dynamicSmemBytes = HEAD_SMEM_BYTES;
    cfg.stream = 0;
    cfg.attrs = attrs;
    cfg.numAttrs = 1;
    cudaLaunchKernelEx(&cfg, head_kernel, pos, attmap, fmw, fmb, lmw, lmb,
                       o1w, o1b, o2w, o2b, o3w, o3b, (float*)d_out);
}

// round 16
// speedup vs baseline: 1.0022x; 1.0022x over previous
#include <cuda_runtime.h>
#include <cstdint>

#define NB 32
#define NIMG 640
#define CH 50176
#define IMG_SZ 150528

__device__ float g_backbone[2 * NIMG * 6];

// backbone dynamic smem layout (floats)
#define O_BUF    0
#define O_CONV   9408
#define O_POOL1  11424
#define O_W2     15532
#define O_B1     15560
#define O_B2     15563
#define O_LW     15564
#define O_LB     15780
#define O_MBAR   15786
#define SMEM_FLOATS 15790
#define SMEM_BYTES  (SMEM_FLOATS * 4)

#define STRIP_BYTES 18816

// head dynamic smem layout (floats): 4-deep weight ring (R13 layout)
#define HF_WBUF  0        // 4 x 6480 floats (25920 B each)
#define HF_FEAT  25920    // 360
#define HF_H1P   26280    // 4 x 180
#define HF_H1    27000    // 180
#define HF_H2P   27180    // 12 x 60
#define HF_H2    27900    // 60
#define HF_H3P   27960    // 36
#define HF_MBAR  27996    // 4 x u64 (8B aligned)
#define HEAD_SMEM_FLOATS 28004
#define HEAD_SMEM_BYTES  (HEAD_SMEM_FLOATS * 4)

#define CH1_FLOATS 6480     // 36 rows x 180
#define CH1_BYTES  25920
#define CH2_BYTES  21600    // 90 rows x 60

__device__ __forceinline__ uint32_t s2u(const void* p) {
    uint32_t a;
    asm("{ .reg .u64 t; cvta.to.shared.u64 t, %1; cvt.u32.u64 %0, t; }" : "=r"(a) : "l"(p));
    return a;
}
__device__ __forceinline__ void mbar_init(uint32_t a, uint32_t cnt) {
    asm volatile("mbarrier.init.shared.b64 [%0], %1;" :: "r"(a), "r"(cnt) : "memory");
}
__device__ __forceinline__ void mbar_expect(uint32_t a, uint32_t tx) {
    asm volatile("mbarrier.arrive.expect_tx.shared.b64 _, [%0], %1;" :: "r"(a), "r"(tx) : "memory");
}
__device__ __forceinline__ void mbar_wait(uint32_t a, uint32_t par) {
    asm volatile(
        "{\n\t.reg .pred P;\n"
        "WL%=:\n\t"
        "mbarrier.try_wait.parity.acquire.cta.shared::cta.b64 P, [%0], %1, 0x989680;\n\t"
        "@!P bra WL%=;\n\t}"
        :: "r"(a), "r"(par) : "memory");
}
__device__ __forceinline__ void bulk_g2s(uint32_t dst, const float* src,
                                         uint32_t bytes, uint32_t mbar) {
    asm volatile(
        "cp.async.bulk.shared::cluster.global.mbarrier::complete_tx::bytes "
        "[%0], [%1], %2, [%3];"
        :: "r"(dst), "l"(src), "r"(bytes), "r"(mbar) : "memory");
}
__device__ __forceinline__ void l2_prefetch(const float* p) {
    asm volatile("prefetch.global.L2 [%0];" :: "l"(p));
}

__device__ __forceinline__ void issue_strip(uint32_t bufb, int buf, const float* src,
                                            uint32_t mbar) {
    mbar_expect(mbar, STRIP_BYTES);
    uint32_t dst = bufb + (uint32_t)buf * STRIP_BYTES;
    #pragma unroll
    for (int ic = 0; ic < 3; ic++)
        bulk_g2s(dst + ic * 6272, src + ic * CH, 6272, mbar);
}

__global__ __launch_bounds__(128)
void backbone_kernel(const float* __restrict__ nodes,
                     const float* __restrict__ depths,
                     const float* __restrict__ c1w,  const float* __restrict__ c1b,
                     const float* __restrict__ c2w,  const float* __restrict__ c2b,
                     const float* __restrict__ lw,   const float* __restrict__ lb,
                     const float* __restrict__ dc1w, const float* __restrict__ dc1b,
                     const float* __restrict__ dc2w, const float* __restrict__ dc2b,
                     const float* __restrict__ dlw,  const float* __restrict__ dlb,
                     const float* __restrict__ o1w,  const float* __restrict__ o2w)
{
    extern __shared__ float sm[];
    const int img = blockIdx.x;
    const int bb  = blockIdx.y;
    const int tid = threadIdx.x;

    const float* in  = (bb == 0 ? nodes : depths) + (size_t)img * IMG_SZ;
    const float* w1  = bb == 0 ? c1w : dc1w;
    const float* b1  = bb == 0 ? c1b : dc1b;
    const float* w2  = bb == 0 ? c2w : dc2w;
    const float* b2  = bb == 0 ? c2b : dc2b;
    const float* lwp = bb == 0 ? lw  : dlw;
    const float* lbp = bb == 0 ? lb  : dlb;

    const uint32_t bufb = s2u(sm + O_BUF);
    const uint32_t mb0  = s2u(sm + O_MBAR);
    const uint32_t mb1  = mb0 + 8;

    float W[81];
    #pragma unroll
    for (int i = 0; i < 81; i++) W[i] = __ldg(w1 + i);

    if (tid < 27) sm[O_W2 + tid] = w2[tid];
    if (tid < 3)  sm[O_B1 + tid] = b1[tid];
    if (tid == 0) sm[O_B2] = b2[0];
    for (int t = tid; t < 216; t += 128) sm[O_LW + t] = lwp[t];
    if (tid < 6)  sm[O_LB + tid] = lbp[tid];

    if (tid == 0) {
        mbar_init(mb0, 1);
        mbar_init(mb1, 1);
        asm volatile("fence.proxy.async.shared::cta;" ::: "memory");
    }
    __syncthreads();

    if (tid == 0) {
        issue_strip(bufb, 0, in, mb0);
        issue_strip(bufb, 1, in + 6 * 224, mb1);
    }

    for (int pr = 0; pr < 37; pr++) {
        const int b = pr & 1;
        mbar_wait(b ? mb1 : mb0, (pr >> 1) & 1);

        if (tid < 111) {
            const int x = tid;
            float a[3][3] = {{0.f,0.f,0.f},{0.f,0.f,0.f},{0.f,0.f,0.f}};
            #pragma unroll
            for (int ic = 0; ic < 3; ic++) {
                const float* rp = sm + O_BUF + b * 4704 + ic * 1568 + 2 * x;
                #pragma unroll
                for (int r = 0; r < 7; r++) {
                    float2 p = *reinterpret_cast<const float2*>(rp + r * 224);
                    float  q = rp[r * 224 + 2];
                    #pragma unroll
                    for (int j = 0; j < 3; j++) {
                        const int ky = r - 2 * j;
                        if (ky >= 0 && ky < 3) {
                            #pragma unroll
                            for (int oc = 0; oc < 3; oc++) {
                                const int wb = (oc * 3 + ic) * 9 + ky * 3;
                                a[j][oc] = fmaf(p.x, W[wb],
                                           fmaf(p.y, W[wb + 1],
                                           fmaf(q,   W[wb + 2], a[j][oc])));
                            }
                        }
                    }
                }
            }
            #pragma unroll
            for (int j = 0; j < 3; j++)
                #pragma unroll
                for (int oc = 0; oc < 3; oc++)
                    sm[O_CONV + b * 1008 + (oc * 3 + j) * 112 + x] = a[j][oc];
        }
        __syncthreads();

        if (tid == 0 && pr + 2 < 37)
            issue_strip(bufb, b, in + 6 * (pr + 2) * 224, b ? mb1 : mb0);

        if (tid < 111) {
            const int oc = tid / 37, px = tid % 37;
            float m = -1e30f;
            #pragma unroll
            for (int j = 0; j < 3; j++)
                #pragma unroll
                for (int i = 0; i < 3; i++)
                    m = fmaxf(m, sm[O_CONV + b * 1008 + (oc * 3 + j) * 112 + 3 * px + i]);
            sm[O_POOL1 + (oc * 37 + pr) * 37 + px] = fmaxf(m + sm[O_B1 + oc], 0.f);
        }
    }
    __syncthreads();

    for (int t2 = tid; t2 < 324; t2 += 128) {
        int cy = t2 / 18, cx = t2 % 18;
        float acc = 0.f;
        #pragma unroll
        for (int ic = 0; ic < 3; ic++)
            #pragma unroll
            for (int ky = 0; ky < 3; ky++)
                #pragma unroll
                for (int kx = 0; kx < 3; kx++)
                    acc = fmaf(sm[O_W2 + (ic * 3 + ky) * 3 + kx],
                               sm[O_POOL1 + (ic * 37 + 2 * cy + ky) * 37 + 2 * cx + kx],
                               acc);
        sm[O_CONV + t2] = acc;
    }
    __syncthreads();

    if (tid < 36) {
        int py = tid / 6, px = tid % 6;
        float m = -1e30f;
        #pragma unroll
        for (int i = 0; i < 3; i++)
            #pragma unroll
            for (int j = 0; j < 3; j++)
                m = fmaxf(m, sm[O_CONV + (3 * py + i) * 18 + 3 * px + j]);
        sm[O_CONV + 400 + tid] = fmaxf(m + sm[O_B2], 0.f);
    }
    __syncthreads();

    if (tid < 6) {
        float acc = sm[O_LB + tid];
        #pragma unroll
        for (int i = 0; i < 36; i++)
            acc = fmaf(sm[O_CONV + 400 + i], sm[O_LW + i * 6 + tid], acc);
        g_backbone[bb * (NIMG * 6) + img * 6 + tid] = acc;
    }

    // ---- tail L2 warm-up for the head's MLP weights -------------------------
    // CTAs with img >= 600 (bids 1200..1279) launch and finish LAST; their
    // epilogue prefetch survives in L2 until head_kernel starts.
    if (img >= 600) {
        const int idx = (img - 600) * 2 + bb;        // 0..79
        if (tid < 26) {                              // o1w: 2025 lines of 128B
            int line = idx * 26 + tid;
            if (line < 2025) l2_prefetch(o1w + line * 32);
        } else if (tid < 31) {                       // o2w: 338 lines
            int line = idx * 5 + (tid - 26);
            if (line < 338) l2_prefetch(o2w + line * 32);
        }
    }
}

// ---------------------------------------------------------------------------
// Head: R13 4-deep TMA weight ring (best measured variant: 10.66 us).
// ---------------------------------------------------------------------------
__global__ __launch_bounds__(768)
void head_kernel(const float* __restrict__ pos,  const float* __restrict__ attmap,
                 const float* __restrict__ fmw,  const float* __restrict__ fmb,
                 const float* __restrict__ lmw,  const float* __restrict__ lmb,
                 const float* __restrict__ o1w,  const float* __restrict__ o1b,
                 const float* __restrict__ o2w,  const float* __restrict__ o2b,
                 const float* __restrict__ o3w,  const float* __restrict__ o3b,
                 float* __restrict__ out)
{
    extern __shared__ float hs[];
    const int bx = blockIdx.x;
    const int t  = threadIdx.x;

    const uint32_t wb  = s2u(hs + HF_WBUF);
    const uint32_t mbb = s2u(hs + HF_MBAR);

    if (t == 0) {
        #pragma unroll
        for (int i = 0; i < 4; i++) mbar_init(mbb + 8 * i, 1);
        asm volatile("fence.proxy.async.shared::cta;" ::: "memory");
        #pragma unroll
        for (int c = 0; c < 4; c++) {
            mbar_expect(mbb + 8 * c, CH1_BYTES);
            bulk_g2s(wb + c * CH1_BYTES, o1w + c * CH1_FLOATS, CH1_BYTES, mbb + 8 * c);
        }
    }

    // backbone-independent message passing (warps 12-15)
    if (t >= 384 && t < 504) {
        int tt = t - 384;
        int f = tt / 24, n = (tt % 24) / 6, d = tt % 6;
        const float* pb = pos    + bx * 120;
        const float* ab = attmap + bx * 80;
        float acc = 0.f;
        #pragma unroll
        for (int m = 0; m < 4; m++) {
            float pm = __ldg(fmb + d);
            #pragma unroll
            for (int e = 0; e < 6; e++)
                pm = fmaf(__ldg(pb + f * 24 + m * 6 + e), __ldg(fmw + e * 6 + d), pm);
            acc = fmaf(__ldg(ab + f * 16 + m * 4 + n), pm, acc);
        }
        if (f >= 1) {
            float pv = __ldg(lmb + d);
            #pragma unroll
            for (int e = 0; e < 6; e++)
                pv = fmaf(__ldg(pb + (f - 1) * 24 + n * 6 + e), __ldg(lmw + e * 6 + d), pv);
            acc += pv;
        }
        hs[HF_FEAT + (f * 4 + n) * 18 + 12 + d] = acc;
    }

    asm volatile("griddepcontrol.wait;" ::: "memory");

    if (t < 120) {
        int f = t / 24, m = (t % 24) / 6, d = t % 6;
        int fm = f * 4 + m;
        int gi = ((bx * 5 + f) * 4 + m) * 6 + d;
        hs[HF_FEAT + fm * 18 + d]     = g_backbone[gi];
        hs[HF_FEAT + fm * 18 + 6 + d] = g_backbone[NIMG * 6 + gi];
    }
    __syncthreads();

    // layer 1: 360 -> 180 over 10 chunks of 36 rows (4-deep ring)
    const int o1 = t % 180;
    const int s1 = t / 180;
    float acc1 = 0.f;
    for (int c = 0; c < 10; c++) {
        const int b = c & 3;
        mbar_wait(mbb + 8 * b, (c >> 2) & 1);
        if (t < 720) {
            const float* wrow = hs + HF_WBUF + b * CH1_FLOATS + (9 * s1) * 180 + o1;
            const float* vp   = hs + HF_FEAT + 36 * c + 9 * s1;
            #pragma unroll
            for (int i = 0; i < 9; i++)
                acc1 = fmaf(vp[i], wrow[i * 180], acc1);
        }
        __syncthreads();
        if (t == 0) {
            const int cn = c + 4;
            if (cn < 10) {
                mbar_expect(mbb + 8 * b, CH1_BYTES);
                bulk_g2s(wb + b * CH1_BYTES, o1w + cn * CH1_FLOATS, CH1_BYTES, mbb + 8 * b);
            } else if (cn == 10) {       // o2w rows 0-89 -> buffer 2
                mbar_expect(mbb + 8 * 2, CH2_BYTES);
                bulk_g2s(wb + 2 * CH1_BYTES, o2w, CH2_BYTES, mbb + 8 * 2);
            } else if (cn == 11) {       // o2w rows 90-179 -> buffer 3
                mbar_expect(mbb + 8 * 3, CH2_BYTES);
                bulk_g2s(wb + 3 * CH1_BYTES, o2w + 5400, CH2_BYTES, mbb + 8 * 3);
            }
        }
    }
    if (t < 720) hs[HF_H1P + s1 * 180 + o1] = acc1;
    __syncthreads();

    if (t < 180) {
        float a = o1b[t];
        #pragma unroll
        for (int s = 0; s < 4; s++) a += hs[HF_H1P + s * 180 + t];
        hs[HF_H1 + t] = fmaxf(a, 0.f);
    }
    __syncthreads();

    // layer 2: 180 -> 60 from chunks 10 (buf2) and 11 (buf3), parity 0
    mbar_wait(mbb + 8 * 2, 0);
    mbar_wait(mbb + 8 * 3, 0);
    if (t < 720) {
        const int o2 = t % 60, s2 = t / 60;
        const int half = (s2 >= 6);
        const int row0 = 15 * s2 - half * 90;
        float a2 = 0.f;
        const float* wrow = hs + HF_WBUF + (2 + half) * CH1_FLOATS + row0 * 60 + o2;
        const float* vp   = hs + HF_H1 + 15 * s2;
        #pragma unroll
        for (int i = 0; i < 15; i++)
            a2 = fmaf(vp[i], wrow[i * 60], a2);
        hs[HF_H2P + s2 * 60 + o2] = a2;
    }
    __syncthreads();

    if (t < 60) {
        float a = o2b[t];
        #pragma unroll
        for (int s = 0; s < 12; s++) a += hs[HF_H2P + s * 60 + t];
        hs[HF_H2 + t] = fmaxf(a, 0.f);
    }
    __syncthreads();

    if (t < 36) {
        int q = t / 6, o = t - q * 6;
        int base = q * 10;
        float a = 0.f;
        #pragma unroll
        for (int i = 0; i < 10; i++)
            a = fmaf(hs[HF_H2 + base + i], __ldg(o3w + (base + i) * 6 + o), a);
        hs[HF_H3P + q * 6 + o] = a;
    }
    __syncthreads();
    if (t < 6) {
        float a = o3b[t];
        #pragma unroll
        for (int q = 0; q < 6; q++) a += hs[HF_H3P + q * 6 + t];
        out[bx * 6 + t] = a;
    }
}

extern "C" void kernel_launch(void* const* d_in, const int* in_sizes, int n_in,
                              void* d_out, int out_size)
{
    const float* nodes  = (const float*)d_in[0];
    const float* pos    = (const float*)d_in[1];
    const float* attmap = (const float*)d_in[2];
    const float* depths = (const float*)d_in[3];
    const float* c1w  = (const float*)d_in[4];
    const float* c1b  = (const float*)d_in[5];
    const float* c2w  = (const float*)d_in[6];
    const float* c2b  = (const float*)d_in[7];
    const float* lw   = (const float*)d_in[8];
    const float* lb   = (const float*)d_in[9];
    const float* dc1w = (const float*)d_in[10];
    const float* dc1b = (const float*)d_in[11];
    const float* dc2w = (const float*)d_in[12];
    const float* dc2b = (const float*)d_in[13];
    const float* dlw  = (const float*)d_in[14];
    const float* dlb  = (const float*)d_in[15];
    const float* fmw  = (const float*)d_in[16];
    const float* fmb  = (const float*)d_in[17];
    const float* lmw  = (const float*)d_in[18];
    const float* lmb  = (const float*)d_in[19];
    const float* o1w  = (const float*)d_in[20];
    const float* o1b  = (const float*)d_in[21];
    const float* o2w  = (const float*)d_in[22];
    const float* o2b  = (const float*)d_in[23];
    const float* o3w  = (const float*)d_in[24];
    const float* o3b  = (const float*)d_in[25];

    cudaFuncSetAttribute(backbone_kernel,
                         cudaFuncAttributeMaxDynamicSharedMemorySize, SMEM_BYTES);
    cudaFuncSetAttribute(head_kernel,
                         cudaFuncAttributeMaxDynamicSharedMemorySize, HEAD_SMEM_BYTES);

    backbone_kernel<<<dim3(NIMG, 2), 128, SMEM_BYTES>>>(
        nodes, depths, c1w, c1b, c2w, c2b, lw, lb,
        dc1w, dc1b, dc2w, dc2b, dlw, dlb, o1w, o2w);

    cudaLaunchAttribute attrs[1];
    attrs[0].id = cudaLaunchAttributeProgrammaticStreamSerialization;
    attrs[0].val.programmaticStreamSerializationAllowed = 1;
    cudaLaunchConfig_t cfg = {};
    cfg.gridDim = dim3(NB);
    cfg.blockDim = dim3(768);
    cfg.dynamicSmemBytes = HEAD_SMEM_BYTES;
    cfg.stream = 0;
    cfg.attrs = attrs;
    cfg.numAttrs = 1;
    cudaLaunchKernelEx(&cfg, head_kernel, pos, attmap, fmw, fmb, lmw, lmb,
                       o1w, o1b, o2w, o2b, o3w, o3b, (float*)d_out);
}

// round 17
// speedup vs baseline: 1.0175x; 1.0153x over previous
#include <cuda_runtime.h>
#include <cstdint>

#define NB 32
#define NIMG 640
#define CH 50176
#define IMG_SZ 150528

__device__ float g_backbone[2 * NIMG * 6];

// backbone dynamic smem layout (floats)
#define O_BUF    0
#define O_CONV   9408
#define O_POOL1  11424
#define O_W2     15532
#define O_B1     15560
#define O_B2     15563
#define O_LW     15564
#define O_LB     15780
#define O_MBAR   15786
#define SMEM_FLOATS 15790
#define SMEM_BYTES  (SMEM_FLOATS * 4)

#define STRIP_BYTES 18816

// head dynamic smem layout (floats): 4-deep weight ring
#define HF_WBUF  0        // 4 x 6480 floats (25920 B each)
#define HF_FEAT  25920    // 360
#define HF_H1P   26280    // 4 x 180
#define HF_H1    27000    // 180
#define HF_H2P   27180    // 12 x 60
#define HF_H2    27900    // 60
#define HF_H3P   27960    // 36
#define HF_MBAR  27996    // 4 x u64 (8B aligned)
#define HEAD_SMEM_FLOATS 28004
#define HEAD_SMEM_BYTES  (HEAD_SMEM_FLOATS * 4)

#define CH1_FLOATS 6480     // 36 rows x 180
#define CH1_BYTES  25920
#define CH2_BYTES  21600    // 90 rows x 60

__device__ __forceinline__ uint32_t s2u(const void* p) {
    uint32_t a;
    asm("{ .reg .u64 t; cvta.to.shared.u64 t, %1; cvt.u32.u64 %0, t; }" : "=r"(a) : "l"(p));
    return a;
}
__device__ __forceinline__ void mbar_init(uint32_t a, uint32_t cnt) {
    asm volatile("mbarrier.init.shared.b64 [%0], %1;" :: "r"(a), "r"(cnt) : "memory");
}
__device__ __forceinline__ void mbar_expect(uint32_t a, uint32_t tx) {
    asm volatile("mbarrier.arrive.expect_tx.shared.b64 _, [%0], %1;" :: "r"(a), "r"(tx) : "memory");
}
__device__ __forceinline__ void mbar_wait(uint32_t a, uint32_t par) {
    asm volatile(
        "{\n\t.reg .pred P;\n"
        "WL%=:\n\t"
        "mbarrier.try_wait.parity.acquire.cta.shared::cta.b64 P, [%0], %1, 0x989680;\n\t"
        "@!P bra WL%=;\n\t}"
        :: "r"(a), "r"(par) : "memory");
}
__device__ __forceinline__ void bulk_g2s(uint32_t dst, const float* src,
                                         uint32_t bytes, uint32_t mbar) {
    asm volatile(
        "cp.async.bulk.shared::cluster.global.mbarrier::complete_tx::bytes "
        "[%0], [%1], %2, [%3];"
        :: "r"(dst), "l"(src), "r"(bytes), "r"(mbar) : "memory");
}
__device__ __forceinline__ void l2_prefetch(const float* p) {
    asm volatile("prefetch.global.L2 [%0];" :: "l"(p));
}

__device__ __forceinline__ void issue_strip(uint32_t bufb, int buf, const float* src,
                                            uint32_t mbar) {
    mbar_expect(mbar, STRIP_BYTES);
    uint32_t dst = bufb + (uint32_t)buf * STRIP_BYTES;
    #pragma unroll
    for (int ic = 0; ic < 3; ic++)
        bulk_g2s(dst + ic * 6272, src + ic * CH, 6272, mbar);
}

__global__ __launch_bounds__(128)
void backbone_kernel(const float* __restrict__ nodes,
                     const float* __restrict__ depths,
                     const float* __restrict__ c1w,  const float* __restrict__ c1b,
                     const float* __restrict__ c2w,  const float* __restrict__ c2b,
                     const float* __restrict__ lw,   const float* __restrict__ lb,
                     const float* __restrict__ dc1w, const float* __restrict__ dc1b,
                     const float* __restrict__ dc2w, const float* __restrict__ dc2b,
                     const float* __restrict__ dlw,  const float* __restrict__ dlb,
                     const float* __restrict__ o1w,  const float* __restrict__ o2w,
                     const float* __restrict__ o3w)
{
    extern __shared__ float sm[];
    const int img = blockIdx.x;
    const int bb  = blockIdx.y;
    const int tid = threadIdx.x;

    const float* in  = (bb == 0 ? nodes : depths) + (size_t)img * IMG_SZ;
    const float* w1  = bb == 0 ? c1w : dc1w;
    const float* b1  = bb == 0 ? c1b : dc1b;
    const float* w2  = bb == 0 ? c2w : dc2w;
    const float* b2  = bb == 0 ? c2b : dc2b;
    const float* lwp = bb == 0 ? lw  : dlw;
    const float* lbp = bb == 0 ? lb  : dlb;

    const uint32_t bufb = s2u(sm + O_BUF);
    const uint32_t mb0  = s2u(sm + O_MBAR);
    const uint32_t mb1  = mb0 + 8;

    float W[81];
    #pragma unroll
    for (int i = 0; i < 81; i++) W[i] = __ldg(w1 + i);

    if (tid < 27) sm[O_W2 + tid] = w2[tid];
    if (tid < 3)  sm[O_B1 + tid] = b1[tid];
    if (tid == 0) sm[O_B2] = b2[0];
    for (int t = tid; t < 216; t += 128) sm[O_LW + t] = lwp[t];
    if (tid < 6)  sm[O_LB + tid] = lbp[tid];

    if (tid == 0) {
        mbar_init(mb0, 1);
        mbar_init(mb1, 1);
        asm volatile("fence.proxy.async.shared::cta;" ::: "memory");
    }
    __syncthreads();

    if (tid == 0) {
        issue_strip(bufb, 0, in, mb0);
        issue_strip(bufb, 1, in + 6 * 224, mb1);
    }

    for (int pr = 0; pr < 37; pr++) {
        const int b = pr & 1;
        mbar_wait(b ? mb1 : mb0, (pr >> 1) & 1);

        if (tid < 111) {
            const int x = tid;
            float a[3][3] = {{0.f,0.f,0.f},{0.f,0.f,0.f},{0.f,0.f,0.f}};
            #pragma unroll
            for (int ic = 0; ic < 3; ic++) {
                const float* rp = sm + O_BUF + b * 4704 + ic * 1568 + 2 * x;
                #pragma unroll
                for (int r = 0; r < 7; r++) {
                    float2 p = *reinterpret_cast<const float2*>(rp + r * 224);
                    float  q = rp[r * 224 + 2];
                    #pragma unroll
                    for (int j = 0; j < 3; j++) {
                        const int ky = r - 2 * j;
                        if (ky >= 0 && ky < 3) {
                            #pragma unroll
                            for (int oc = 0; oc < 3; oc++) {
                                const int wb = (oc * 3 + ic) * 9 + ky * 3;
                                a[j][oc] = fmaf(p.x, W[wb],
                                           fmaf(p.y, W[wb + 1],
                                           fmaf(q,   W[wb + 2], a[j][oc])));
                            }
                        }
                    }
                }
            }
            #pragma unroll
            for (int j = 0; j < 3; j++)
                #pragma unroll
                for (int oc = 0; oc < 3; oc++)
                    sm[O_CONV + b * 1008 + (oc * 3 + j) * 112 + x] = a[j][oc];
        }
        __syncthreads();

        if (tid == 0 && pr + 2 < 37)
            issue_strip(bufb, b, in + 6 * (pr + 2) * 224, b ? mb1 : mb0);

        if (tid < 111) {
            const int oc = tid / 37, px = tid % 37;
            float m = -1e30f;
            #pragma unroll
            for (int j = 0; j < 3; j++)
                #pragma unroll
                for (int i = 0; i < 3; i++)
                    m = fmaxf(m, sm[O_CONV + b * 1008 + (oc * 3 + j) * 112 + 3 * px + i]);
            sm[O_POOL1 + (oc * 37 + pr) * 37 + px] = fmaxf(m + sm[O_B1 + oc], 0.f);
        }
    }
    __syncthreads();

    for (int t2 = tid; t2 < 324; t2 += 128) {
        int cy = t2 / 18, cx = t2 % 18;
        float acc = 0.f;
        #pragma unroll
        for (int ic = 0; ic < 3; ic++)
            #pragma unroll
            for (int ky = 0; ky < 3; ky++)
                #pragma unroll
                for (int kx = 0; kx < 3; kx++)
                    acc = fmaf(sm[O_W2 + (ic * 3 + ky) * 3 + kx],
                               sm[O_POOL1 + (ic * 37 + 2 * cy + ky) * 37 + 2 * cx + kx],
                               acc);
        sm[O_CONV + t2] = acc;
    }
    __syncthreads();

    if (tid < 36) {
        int py = tid / 6, px = tid % 6;
        float m = -1e30f;
        #pragma unroll
        for (int i = 0; i < 3; i++)
            #pragma unroll
            for (int j = 0; j < 3; j++)
                m = fmaxf(m, sm[O_CONV + (3 * py + i) * 18 + 3 * px + j]);
        sm[O_CONV + 400 + tid] = fmaxf(m + sm[O_B2], 0.f);
    }
    __syncthreads();

    if (tid < 6) {
        float acc = sm[O_LB + tid];
        #pragma unroll
        for (int i = 0; i < 36; i++)
            acc = fmaf(sm[O_CONV + 400 + i], sm[O_LW + i * 6 + tid], acc);
        g_backbone[bb * (NIMG * 6) + img * 6 + tid] = acc;
    }

    // ---- tail L2 warm-up for the head's MLP weights (last-launched CTAs) ----
    if (img >= 600) {
        const int idx = (img - 600) * 2 + bb;        // 0..79
        if (tid < 26) {                              // o1w: 2025 lines of 128B
            int line = idx * 26 + tid;
            if (line < 2025) l2_prefetch(o1w + line * 32);
        } else if (tid < 31) {                       // o2w: 338 lines
            int line = idx * 5 + (tid - 26);
            if (line < 338) l2_prefetch(o2w + line * 32);
        } else if (tid < 43 && idx == 0) {           // o3w: 12 lines
            l2_prefetch(o3w + (tid - 31) * 32);
        }
    }
}

// ---------------------------------------------------------------------------
// Head: 4-deep TMA weight ring (best measured head: 10.66 us).
// ---------------------------------------------------------------------------
__global__ __launch_bounds__(768)
void head_kernel(const float* __restrict__ pos,  const float* __restrict__ attmap,
                 const float* __restrict__ fmw,  const float* __restrict__ fmb,
                 const float* __restrict__ lmw,  const float* __restrict__ lmb,
                 const float* __restrict__ o1w,  const float* __restrict__ o1b,
                 const float* __restrict__ o2w,  const float* __restrict__ o2b,
                 const float* __restrict__ o3w,  const float* __restrict__ o3b,
                 float* __restrict__ out)
{
    extern __shared__ float hs[];
    const int bx = blockIdx.x;
    const int t  = threadIdx.x;

    const uint32_t wb  = s2u(hs + HF_WBUF);
    const uint32_t mbb = s2u(hs + HF_MBAR);

    if (t == 0) {
        #pragma unroll
        for (int i = 0; i < 4; i++) mbar_init(mbb + 8 * i, 1);
        asm volatile("fence.proxy.async.shared::cta;" ::: "memory");
        #pragma unroll
        for (int c = 0; c < 4; c++) {
            mbar_expect(mbb + 8 * c, CH1_BYTES);
            bulk_g2s(wb + c * CH1_BYTES, o1w + c * CH1_FLOATS, CH1_BYTES, mbb + 8 * c);
        }
    }

    // small-tensor prefetch (biases + o3w) so late phases hit L2
    if (t >= 736) {
        int k = t - 736;                 // 0..31
        if (k < 6)       l2_prefetch(o1b + k * 32);
        else if (k < 9)  l2_prefetch(o2b + (k - 6) * 32);
        else if (k < 21) l2_prefetch(o3w + (k - 9) * 32);
        else if (k == 21) l2_prefetch(o3b);
    }

    // backbone-independent message passing (warps 12-15)
    if (t >= 384 && t < 504) {
        int tt = t - 384;
        int f = tt / 24, n = (tt % 24) / 6, d = tt % 6;
        const float* pb = pos    + bx * 120;
        const float* ab = attmap + bx * 80;
        float acc = 0.f;
        #pragma unroll
        for (int m = 0; m < 4; m++) {
            float pm = __ldg(fmb + d);
            #pragma unroll
            for (int e = 0; e < 6; e++)
                pm = fmaf(__ldg(pb + f * 24 + m * 6 + e), __ldg(fmw + e * 6 + d), pm);
            acc = fmaf(__ldg(ab + f * 16 + m * 4 + n), pm, acc);
        }
        if (f >= 1) {
            float pv = __ldg(lmb + d);
            #pragma unroll
            for (int e = 0; e < 6; e++)
                pv = fmaf(__ldg(pb + (f - 1) * 24 + n * 6 + e), __ldg(lmw + e * 6 + d), pv);
            acc += pv;
        }
        hs[HF_FEAT + (f * 4 + n) * 18 + 12 + d] = acc;
    }

    asm volatile("griddepcontrol.wait;" ::: "memory");

    if (t < 120) {
        int f = t / 24, m = (t % 24) / 6, d = t % 6;
        int fm = f * 4 + m;
        int gi = ((bx * 5 + f) * 4 + m) * 6 + d;
        hs[HF_FEAT + fm * 18 + d]     = g_backbone[gi];
        hs[HF_FEAT + fm * 18 + 6 + d] = g_backbone[NIMG * 6 + gi];
    }
    __syncthreads();

    // layer 1: 360 -> 180 over 10 chunks of 36 rows (4-deep ring)
    const int o1 = t % 180;
    const int s1 = t / 180;
    float acc1 = 0.f;
    for (int c = 0; c < 10; c++) {
        const int b = c & 3;
        mbar_wait(mbb + 8 * b, (c >> 2) & 1);
        if (t < 720) {
            const float* wrow = hs + HF_WBUF + b * CH1_FLOATS + (9 * s1) * 180 + o1;
            const float* vp   = hs + HF_FEAT + 36 * c + 9 * s1;
            #pragma unroll
            for (int i = 0; i < 9; i++)
                acc1 = fmaf(vp[i], wrow[i * 180], acc1);
        }
        __syncthreads();
        if (t == 0) {
            const int cn = c + 4;
            if (cn < 10) {
                mbar_expect(mbb + 8 * b, CH1_BYTES);
                bulk_g2s(wb + b * CH1_BYTES, o1w + cn * CH1_FLOATS, CH1_BYTES, mbb + 8 * b);
            } else if (cn == 10) {       // o2w rows 0-89 -> buffer 2
                mbar_expect(mbb + 8 * 2, CH2_BYTES);
                bulk_g2s(wb + 2 * CH1_BYTES, o2w, CH2_BYTES, mbb + 8 * 2);
            } else if (cn == 11) {       // o2w rows 90-179 -> buffer 3
                mbar_expect(mbb + 8 * 3, CH2_BYTES);
                bulk_g2s(wb + 3 * CH1_BYTES, o2w + 5400, CH2_BYTES, mbb + 8 * 3);
            }
        }
    }
    if (t < 720) hs[HF_H1P + s1 * 180 + o1] = acc1;
    __syncthreads();

    if (t < 180) {
        float a = o1b[t];
        #pragma unroll
        for (int s = 0; s < 4; s++) a += hs[HF_H1P + s * 180 + t];
        hs[HF_H1 + t] = fmaxf(a, 0.f);
    }
    __syncthreads();

    // layer 2: 180 -> 60 from chunks 10 (buf2) and 11 (buf3), parity 0
    mbar_wait(mbb + 8 * 2, 0);
    mbar_wait(mbb + 8 * 3, 0);
    if (t < 720) {
        const int o2 = t % 60, s2 = t / 60;
        const int half = (s2 >= 6);
        const int row0 = 15 * s2 - half * 90;
        float a2 = 0.f;
        const float* wrow = hs + HF_WBUF + (2 + half) * CH1_FLOATS + row0 * 60 + o2;
        const float* vp   = hs + HF_H1 + 15 * s2;
        #pragma unroll
        for (int i = 0; i < 15; i++)
            a2 = fmaf(vp[i], wrow[i * 60], a2);
        hs[HF_H2P + s2 * 60 + o2] = a2;
    }
    __syncthreads();

    if (t < 60) {
        float a = o2b[t];
        #pragma unroll
        for (int s = 0; s < 12; s++) a += hs[HF_H2P + s * 60 + t];
        hs[HF_H2 + t] = fmaxf(a, 0.f);
    }
    __syncthreads();

    if (t < 36) {
        int q = t / 6, o = t - q * 6;
        int base = q * 10;
        float a = 0.f;
        #pragma unroll
        for (int i = 0; i < 10; i++)
            a = fmaf(hs[HF_H2 + base + i], __ldg(o3w + (base + i) * 6 + o), a);
        hs[HF_H3P + q * 6 + o] = a;
    }
    __syncthreads();
    if (t < 6) {
        float a = o3b[t];
        #pragma unroll
        for (int q = 0; q < 6; q++) a += hs[HF_H3P + q * 6 + t];
        out[bx * 6 + t] = a;
    }
}

extern "C" void kernel_launch(void* const* d_in, const int* in_sizes, int n_in,
                              void* d_out, int out_size)
{
    const float* nodes  = (const float*)d_in[0];
    const float* pos    = (const float*)d_in[1];
    const float* attmap = (const float*)d_in[2];
    const float* depths = (const float*)d_in[3];
    const float* c1w  = (const float*)d_in[4];
    const float* c1b  = (const float*)d_in[5];
    const float* c2w  = (const float*)d_in[6];
    const float* c2b  = (const float*)d_in[7];
    const float* lw   = (const float*)d_in[8];
    const float* lb   = (const float*)d_in[9];
    const float* dc1w = (const float*)d_in[10];
    const float* dc1b = (const float*)d_in[11];
    const float* dc2w = (const float*)d_in[12];
    const float* dc2b = (const float*)d_in[13];
    const float* dlw  = (const float*)d_in[14];
    const float* dlb  = (const float*)d_in[15];
    const float* fmw  = (const float*)d_in[16];
    const float* fmb  = (const float*)d_in[17];
    const float* lmw  = (const float*)d_in[18];
    const float* lmb  = (const float*)d_in[19];
    const float* o1w  = (const float*)d_in[20];
    const float* o1b  = (const float*)d_in[21];
    const float* o2w  = (const float*)d_in[22];
    const float* o2b  = (const float*)d_in[23];
    const float* o3w  = (const float*)d_in[24];
    const float* o3b  = (const float*)d_in[25];

    cudaFuncSetAttribute(backbone_kernel,
                         cudaFuncAttributeMaxDynamicSharedMemorySize, SMEM_BYTES);
    cudaFuncSetAttribute(head_kernel,
                         cudaFuncAttributeMaxDynamicSharedMemorySize, HEAD_SMEM_BYTES);

    backbone_kernel<<<dim3(NIMG, 2), 128, SMEM_BYTES>>>(
        nodes, depths, c1w, c1b, c2w, c2b, lw, lb,
        dc1w, dc1b, dc2w, dc2b, dlw, dlb, o1w, o2w, o3w);

    cudaLaunchAttribute attrs[1];
    attrs[0].id = cudaLaunchAttributeProgrammaticStreamSerialization;
    attrs[0].val.programmaticStreamSerializationAllowed = 1;
    cudaLaunchConfig_t cfg = {};
    cfg.gridDim = dim3(NB);
    cfg.blockDim = dim3(768);
    cfg.dynamicSmemBytes = HEAD_SMEM_BYTES;
    cfg.stream = 0;
    cfg.attrs = attrs;
    cfg.numAttrs = 1;
    cudaLaunchKernelEx(&cfg, head_kernel, pos, attmap, fmw, fmb, lmw, lmb,
                       o1w, o1b, o2w, o2b, o3w, o3b, (float*)d_out);
}